// round 15
// baseline (speedup 1.0000x reference)
#include <cuda_runtime.h>
#include <cuda_bf16.h>
#include <cuda_fp16.h>
#include <math.h>

// Problem constants
#define BB   4
#define SS   2048
#define DD   1024
#define HH   16
#define HDIM 64
#define FF   4096
#define MM   (BB*SS)   // 8192 rows
#define LN_EPS 1e-5f

// ===================== low-level helpers =====================
__device__ __forceinline__ unsigned int smem_u32(const void* p) {
    unsigned int a;
    asm("{ .reg .u64 t; cvta.to.shared.u64 t, %1; cvt.u32.u64 %0, t; }" : "=r"(a) : "l"(p));
    return a;
}
__device__ __forceinline__ void cp16(unsigned int s, const void* g) {
    asm volatile("cp.async.cg.shared.global [%0], [%1], 16;" :: "r"(s), "l"(g));
}
#define CP_COMMIT() asm volatile("cp.async.commit_group;" ::: "memory")
#define CP_WAIT1()  asm volatile("cp.async.wait_group 1;" ::: "memory")
#define CP_WAIT2()  asm volatile("cp.async.wait_group 2;" ::: "memory")
#define CP_WAIT0()  asm volatile("cp.async.wait_group 0;" ::: "memory")

__device__ __forceinline__ void ldsm4(unsigned int* r, unsigned int addr) {
    asm volatile("ldmatrix.sync.aligned.m8n8.x4.shared.b16 {%0,%1,%2,%3}, [%4];"
        : "=r"(r[0]), "=r"(r[1]), "=r"(r[2]), "=r"(r[3]) : "r"(addr));
}
__device__ __forceinline__ void ldsm4t(unsigned int* r, unsigned int addr) {
    asm volatile("ldmatrix.sync.aligned.m8n8.x4.trans.shared.b16 {%0,%1,%2,%3}, [%4];"
        : "=r"(r[0]), "=r"(r[1]), "=r"(r[2]), "=r"(r[3]) : "r"(addr));
}
__device__ __forceinline__ void mma_f16(float* c, const unsigned int* a,
                                        unsigned int b0, unsigned int b1) {
    asm volatile("mma.sync.aligned.m16n8k16.row.col.f32.f16.f16.f32 "
        "{%0,%1,%2,%3}, {%4,%5,%6,%7}, {%8,%9}, {%0,%1,%2,%3};"
        : "+f"(c[0]), "+f"(c[1]), "+f"(c[2]), "+f"(c[3])
        : "r"(a[0]), "r"(a[1]), "r"(a[2]), "r"(a[3]), "r"(b0), "r"(b1));
}
__device__ __forceinline__ unsigned int pack_f16(__half a, __half b) {
    return (unsigned int)__half_as_ushort(a) | ((unsigned int)__half_as_ushort(b) << 16);
}
__device__ __forceinline__ unsigned int pack2f(float a, float b) {
    return pack_f16(__float2half(a), __float2half(b));
}

// ===================== scratch (device globals) =====================
__device__ __half g_xf[(size_t)MM*DD];
__device__ __half g_qkvf[(size_t)MM*3072];
__device__ __half g_af[(size_t)MM*DD];         // attention out single fp16
__device__ float g_tmp[(size_t)MM*DD];
__device__ float g_x1[(size_t)MM*DD];
__device__ __half g_x1f[(size_t)MM*DD];
__device__ __half g_h1f[(size_t)MM*FF];
// transposed single-fp16 weights ([N,K] row-major)
__device__ __half g_wqkvf[(size_t)3072*1024];
__device__ __half g_wof[(size_t)1024*1024];
__device__ __half g_winf[(size_t)4096*1024];
__device__ __half g_woutf[(size_t)1024*4096];

// ===================== prep kernels =====================
__global__ void fconvert_kernel(const float* __restrict__ in,
                                __half* __restrict__ o, int n4)
{
    int i = blockIdx.x * blockDim.x + threadIdx.x;
    if (i >= n4) return;
    float4 v = ((const float4*)in)[i];
    ((uint2*)o)[i] = make_uint2(pack2f(v.x, v.y), pack2f(v.z, v.w));
}

// transpose one 32x32 block of W [K,N] -> single fp16 T [N,K]
__device__ __forceinline__ void wsingle_block(const float* __restrict__ W,
                                              __half* __restrict__ T,
                                              int K, int N, int k0, int n0,
                                              float t[32][33])
{
    int tx = threadIdx.x, ty = threadIdx.y;
    #pragma unroll
    for (int i = 0; i < 32; i += 8)
        t[ty + i][tx] = W[(size_t)(k0 + ty + i) * N + n0 + tx];
    __syncthreads();
    #pragma unroll
    for (int i = 0; i < 32; i += 8) {
        float v = t[tx][ty + i];
        T[(size_t)(n0 + ty + i) * K + k0 + tx] = __float2half(v);
    }
}

// FFN weights only: w_in fp16 (4096 blocks), w_out fp16 (4096 blocks)
__global__ void wsplit2_kernel(const float* __restrict__ Win,
                               const float* __restrict__ Wout)
{
    __shared__ float t[32][33];
    int idx = blockIdx.x;
    if (idx < 4096) {
        wsingle_block(Win, g_winf, 1024, 4096,
                      (idx >> 7) * 32, (idx & 127) * 32, t);
    } else {
        int i2 = idx - 4096;
        wsingle_block(Wout, g_woutf, 4096, 1024,
                      (i2 >> 5) * 32, (i2 & 31) * 32, t);
    }
}

// Wo only
__global__ void wsplitWo_kernel(const float* __restrict__ Wo)
{
    __shared__ float t[32][33];
    int idx = blockIdx.x;
    wsingle_block(Wo, g_wof, 1024, 1024, (idx >> 5) * 32, (idx & 31) * 32, t);
}

// Wq/Wk/Wv [H,D,HD] -> combined transposed single fp16 [3072, 1024]
__global__ void qkvT_kernel(const float* __restrict__ Wq,
                            const float* __restrict__ Wk,
                            const float* __restrict__ Wv,
                            __half* __restrict__ T)
{
    __shared__ float t[32][33];
    int z = blockIdx.z;
    int mat = z / HH, h = z - mat * HH;
    const float* W = (mat == 0 ? Wq : mat == 1 ? Wk : Wv) + (size_t)h * DD * HDIM;
    int k0 = blockIdx.y * 32, e0 = blockIdx.x * 32;
    int tx = threadIdx.x, ty = threadIdx.y;
    #pragma unroll
    for (int i = 0; i < 32; i += 8)
        t[ty + i][tx] = W[(size_t)(k0 + ty + i) * HDIM + e0 + tx];
    __syncthreads();
    int nbase = mat * 1024 + h * HDIM;
    #pragma unroll
    for (int i = 0; i < 32; i += 8) {
        float v = t[tx][ty + i];
        T[(size_t)(nbase + e0 + ty + i) * DD + k0 + tx] = __float2half(v);
    }
}

// swizzled byte offset for (row, 16B-chunk ck) within a 128B-row matrix
#define GSW(r, ck) ((unsigned int)((r) * 128 + ((((ck) ^ ((r) & 7))) << 4)))

// ===================== single-fp16 GEMM, 2 CTAs/SM, sw-pipelined ==============
// D = A*B. Block 128x128, 256 threads (8 warps, warp 64x32), K-chunk 64,
// 3-stage (32KB/stage, 96KB) -> 2 CTAs/SM. Register double-buffered frags.
#define G1_A  0
#define G1_B  16384
#define G1_STG 32768
#define G1_SMEM (3*G1_STG)     // 98304

template<bool BIAS, bool RELU, bool F32OUT, bool HALFOUT>
__global__ void __launch_bounds__(256, 2) gemm1_kernel(
    const __half* __restrict__ A,
    const __half* __restrict__ BT,
    const float* __restrict__ bias,
    float* __restrict__ C,
    __half* __restrict__ Ch,
    int M, int N, int K)
{
    extern __shared__ __align__(128) char smem[];
    const unsigned int sb = smem_u32(smem);
    const int tid = threadIdx.x;
    const int row0 = blockIdx.y * 128;
    const int col0 = blockIdx.x * 128;

    const int wid = tid >> 5, lane = tid & 31;
    const int wm0 = (wid & 1) * 64, wn0 = (wid >> 1) * 32;
    const int lr = lane & 15, lh = lane >> 4;

    auto load_stage = [&](int c, int s) {
        unsigned int base = sb + s * G1_STG;
        int k0 = c * 64;
        #pragma unroll
        for (int i = 0; i < 4; i++) {
            int lin = tid + (i << 8);
            int r = lin >> 3, ck = lin & 7;
            unsigned int so = GSW(r, ck);
            cp16(base + G1_A + so, A + (size_t)(row0 + r) * K + k0 + ck * 8);
        }
        #pragma unroll
        for (int i = 0; i < 4; i++) {
            int lin = tid + (i << 8);
            int r = lin >> 3, ck = lin & 7;
            unsigned int so = GSW(r, ck);
            cp16(base + G1_B + so, BT + (size_t)(col0 + r) * K + k0 + ck * 8);
        }
        CP_COMMIT();
    };

    float acc[4][4][4] = {};
    unsigned int a_r[2][4][4], b_r[2][2][4];

    auto load_frags = [&](unsigned int base, int ks, int buf) {
        #pragma unroll
        for (int mt = 0; mt < 4; mt++) {
            int r = wm0 + mt*16 + lr;
            ldsm4(a_r[buf][mt], base + G1_A + GSW(r, ks*2 + lh));
        }
        #pragma unroll
        for (int bt = 0; bt < 2; bt++) {
            int r = wn0 + bt*16 + lr;
            ldsm4(b_r[buf][bt], base + G1_B + GSW(r, ks*2 + lh));
        }
    };

    load_stage(0, 0);
    load_stage(1, 1);
    load_stage(2, 2);

    const int NC = K >> 6;
    for (int c = 0; c < NC; c++) {
        CP_WAIT2();
        __syncthreads();

        unsigned int base = sb + (c % 3) * G1_STG;
        load_frags(base, 0, 0);
        #pragma unroll
        for (int ks = 0; ks < 4; ks++) {
            int cur = ks & 1;
            if (ks < 3) load_frags(base, ks + 1, cur ^ 1);
            #pragma unroll
            for (int mt = 0; mt < 4; mt++)
                #pragma unroll
                for (int nt = 0; nt < 4; nt++)
                    mma_f16(acc[mt][nt], a_r[cur][mt],
                            b_r[cur][nt>>1][nt&1], b_r[cur][nt>>1][(nt&1)+2]);
        }

        __syncthreads();
        if (c + 3 < NC) load_stage(c + 3, (c + 3) % 3);
    }

    // ---- epilogue ----
    const int gq = lane >> 2, pq = lane & 3;
    #pragma unroll
    for (int mt = 0; mt < 4; mt++) {
        #pragma unroll
        for (int nt = 0; nt < 4; nt++) {
            int col = col0 + wn0 + nt*8 + pq*2;
            float b0 = 0.f, b1 = 0.f;
            if (BIAS) { b0 = bias[col]; b1 = bias[col+1]; }
            #pragma unroll
            for (int h2 = 0; h2 < 2; h2++) {
                int row = row0 + wm0 + mt*16 + gq + h2*8;
                float v0 = acc[mt][nt][h2*2+0] + b0;
                float v1 = acc[mt][nt][h2*2+1] + b1;
                if (RELU) { v0 = fmaxf(v0, 0.f); v1 = fmaxf(v1, 0.f); }
                if (F32OUT)
                    *(float2*)(C + (size_t)row * N + col) = make_float2(v0, v1);
                if (HALFOUT)
                    *(unsigned int*)(Ch + (size_t)row * N + col) = pack2f(v0, v1);
            }
        }
    }
}

// ===================== tensor-core causal flash attention (single fp16) =======
#define AP 144
#define KMAT 9216              // 64*AP
#define QMAT 18432             // 128*AP
#define FA_STG (2*KMAT)        // 18432
#define FA_SMEM (QMAT + 2*FA_STG)   // 55296

__global__ void __launch_bounds__(256, 1) flash_tc_kernel()
{
    const int pid = blockIdx.x, bh = blockIdx.y;
    const int b = bh >> 4, h = bh & 15;
    const int tid = threadIdx.x, wid = tid >> 5, lane = tid & 31;
    const int wm = wid * 16;
    const int lr = lane & 15, lh = lane >> 4;

    extern __shared__ __align__(16) char smem[];
    const unsigned int sb = smem_u32(smem);
    const unsigned int sQ = sb;

    for (int run = 0; run < 2; run++) {
        const int qt0 = run ? (15 - pid) : pid;
        const int NKT = 2 * qt0 + 2;

        __syncthreads();

        {
            const __half* q = g_qkvf + (size_t)(b*SS + qt0*128)*3072 + h*HDIM;
            #pragma unroll
            for (int i = 0; i < 4; i++) {
                int lin = tid + (i << 8);
                int r = lin >> 3, ck = lin & 7;
                cp16(sQ + r*AP + ck*16, q + (size_t)r*3072 + ck*8);
            }
            CP_COMMIT();
        }

        auto load_kv = [&](int kt, int s) {
            unsigned int base = sb + QMAT + s * FA_STG;
            size_t rowb = (size_t)(b*SS + kt*64)*3072;
            const __half* k = g_qkvf + rowb + 1024 + h*HDIM;
            const __half* v = g_qkvf + rowb + 2048 + h*HDIM;
            #pragma unroll
            for (int i = 0; i < 2; i++) {
                int lin = tid + (i << 8);
                int r = lin >> 3, ck = lin & 7;
                unsigned int so = r*AP + ck*16;
                size_t g = (size_t)r*3072 + ck*8;
                cp16(base + so,        k + g);
                cp16(base + KMAT + so, v + g);
            }
            CP_COMMIT();
        };

        load_kv(0, 0);
        load_kv(1, 1);

        float o[8][4] = {};
        float m0 = -1e30f, m1 = -1e30f, l0 = 0.f, l1 = 0.f;

        for (int kt = 0; kt < NKT; kt++) {
            if (kt < NKT - 1) CP_WAIT1(); else CP_WAIT0();
            __syncthreads();

            const unsigned int kb = sb + QMAT + (kt & 1) * FA_STG;

            float sc[8][4] = {};
            #pragma unroll
            for (int kd = 0; kd < 4; kd++) {
                unsigned int aq[4];
                unsigned int qro = (unsigned int)(wm + lr)*AP + (kd*2 + lh)*16;
                ldsm4(aq, sQ + qro);
                #pragma unroll
                for (int g = 0; g < 4; g++) {
                    unsigned int rk[4];
                    unsigned int kro = (unsigned int)(g*16 + lr)*AP + (kd*2 + lh)*16;
                    ldsm4(rk, kb + kro);
                    mma_f16(sc[2*g],   aq, rk[0], rk[2]);
                    mma_f16(sc[2*g+1], aq, rk[1], rk[3]);
                }
            }

            if (kt >= 2*qt0) {
                const int grow0 = qt0*128 + wm + (lane >> 2);
                const int gc0 = kt*64 + (lane & 3)*2;
                #pragma unroll
                for (int nt = 0; nt < 8; nt++) {
                    int c0l = gc0 + nt*8;
                    sc[nt][0] = (c0l     > grow0)   ? -1e30f : sc[nt][0]*0.125f;
                    sc[nt][1] = (c0l + 1 > grow0)   ? -1e30f : sc[nt][1]*0.125f;
                    sc[nt][2] = (c0l     > grow0+8) ? -1e30f : sc[nt][2]*0.125f;
                    sc[nt][3] = (c0l + 1 > grow0+8) ? -1e30f : sc[nt][3]*0.125f;
                }
            } else {
                #pragma unroll
                for (int nt = 0; nt < 8; nt++) {
                    sc[nt][0] *= 0.125f; sc[nt][1] *= 0.125f;
                    sc[nt][2] *= 0.125f; sc[nt][3] *= 0.125f;
                }
            }

            float mx0 = -1e30f, mx1 = -1e30f;
            #pragma unroll
            for (int nt = 0; nt < 8; nt++) {
                mx0 = fmaxf(mx0, fmaxf(sc[nt][0], sc[nt][1]));
                mx1 = fmaxf(mx1, fmaxf(sc[nt][2], sc[nt][3]));
            }
            mx0 = fmaxf(mx0, __shfl_xor_sync(0xffffffffu, mx0, 1));
            mx0 = fmaxf(mx0, __shfl_xor_sync(0xffffffffu, mx0, 2));
            mx1 = fmaxf(mx1, __shfl_xor_sync(0xffffffffu, mx1, 1));
            mx1 = fmaxf(mx1, __shfl_xor_sync(0xffffffffu, mx1, 2));
            float mn0 = fmaxf(m0, mx0), mn1 = fmaxf(m1, mx1);
            float cf0 = __expf(m0 - mn0), cf1 = __expf(m1 - mn1);
            m0 = mn0; m1 = mn1;
            float s0 = 0.f, s1 = 0.f;
            #pragma unroll
            for (int nt = 0; nt < 8; nt++) {
                sc[nt][0] = __expf(sc[nt][0] - mn0);
                sc[nt][1] = __expf(sc[nt][1] - mn0);
                sc[nt][2] = __expf(sc[nt][2] - mn1);
                sc[nt][3] = __expf(sc[nt][3] - mn1);
                s0 += sc[nt][0] + sc[nt][1];
                s1 += sc[nt][2] + sc[nt][3];
            }
            s0 += __shfl_xor_sync(0xffffffffu, s0, 1);
            s0 += __shfl_xor_sync(0xffffffffu, s0, 2);
            s1 += __shfl_xor_sync(0xffffffffu, s1, 1);
            s1 += __shfl_xor_sync(0xffffffffu, s1, 2);
            l0 = l0 * cf0 + s0;
            l1 = l1 * cf1 + s1;
            #pragma unroll
            for (int dt = 0; dt < 8; dt++) {
                o[dt][0] *= cf0; o[dt][1] *= cf0;
                o[dt][2] *= cf1; o[dt][3] *= cf1;
            }

            #pragma unroll
            for (int j = 0; j < 4; j++) {
                unsigned int ph[4];
                ph[0] = pack2f(sc[2*j][0],   sc[2*j][1]);
                ph[1] = pack2f(sc[2*j][2],   sc[2*j][3]);
                ph[2] = pack2f(sc[2*j+1][0], sc[2*j+1][1]);
                ph[3] = pack2f(sc[2*j+1][2], sc[2*j+1][3]);
                #pragma unroll
                for (int g = 0; g < 4; g++) {
                    unsigned int rv[4];
                    unsigned int vro = (unsigned int)(j*16 + lr)*AP + (g*2 + lh)*16;
                    ldsm4t(rv, kb + KMAT + vro);
                    mma_f16(o[2*g],   ph, rv[0], rv[1]);
                    mma_f16(o[2*g+1], ph, rv[2], rv[3]);
                }
            }

            __syncthreads();
            if (kt + 2 < NKT) load_kv(kt + 2, kt & 1);
        }

        const float inv0 = 1.f / l0, inv1 = 1.f / l1;
        const int row0g = qt0*128 + wm + (lane >> 2);
        __half* op = g_af + ((size_t)bh*SS)*HDIM;
        #pragma unroll
        for (int dt = 0; dt < 8; dt++) {
            int d = dt*8 + (lane & 3)*2;
            *(unsigned int*)(op + (size_t)row0g*HDIM + d) =
                pack2f(o[dt][0]*inv0, o[dt][1]*inv0);
            *(unsigned int*)(op + (size_t)(row0g+8)*HDIM + d) =
                pack2f(o[dt][2]*inv1, o[dt][3]*inv1);
        }
    }
}

// ===================== LayerNorm =====================
__device__ __forceinline__ float blk_sum(float v, float* sred)
{
    #pragma unroll
    for (int o = 16; o; o >>= 1) v += __shfl_xor_sync(0xffffffffu, v, o);
    int w = threadIdx.x >> 5;
    if ((threadIdx.x & 31) == 0) sred[w] = v;
    __syncthreads();
    float t = (threadIdx.x < 8) ? sred[threadIdx.x] : 0.f;
    if (threadIdx.x < 32) {
        #pragma unroll
        for (int o = 4; o; o >>= 1) t += __shfl_xor_sync(0xffffffffu, t, o);
        if (threadIdx.x == 0) sred[0] = t;
    }
    __syncthreads();
    float r = sred[0];
    __syncthreads();
    return r;
}

template<bool OUTH>
__global__ void ln_kernel(const float* __restrict__ resid,
                          const float* __restrict__ y,
                          const float* __restrict__ gamma,
                          const float* __restrict__ beta,
                          float* __restrict__ outf,
                          __half* __restrict__ oh)
{
    __shared__ float sred[32];
    const int row = blockIdx.x;
    const int tid = threadIdx.x;

    float4 a = ((const float4*)(resid + (size_t)row * DD))[tid];
    float4 b = ((const float4*)(y     + (size_t)row * DD))[tid];
    float4 v = make_float4(a.x + b.x, a.y + b.y, a.z + b.z, a.w + b.w);

    float total = blk_sum(v.x + v.y + v.z + v.w, sred);
    float mu = total * (1.f / DD);

    float dx = v.x - mu, dy = v.y - mu, dz = v.z - mu, dw = v.w - mu;
    float tot2 = blk_sum(dx*dx + dy*dy + dz*dz + dw*dw, sred);
    float inv = rsqrtf(tot2 * (1.f / DD) + LN_EPS);

    float4 g = ((const float4*)gamma)[tid];
    float4 be = ((const float4*)beta)[tid];
    float ov[4];
    ov[0] = dx * inv * g.x + be.x;
    ov[1] = dy * inv * g.y + be.y;
    ov[2] = dz * inv * g.z + be.z;
    ov[3] = dw * inv * g.w + be.w;
    ((float4*)(outf + (size_t)row * DD))[tid] = make_float4(ov[0], ov[1], ov[2], ov[3]);

    if (OUTH) {
        *(uint2*)(oh + (size_t)row * DD + tid * 4) =
            make_uint2(pack2f(ov[0], ov[1]), pack2f(ov[2], ov[3]));
    }
}

// ===================== launch =====================
extern "C" void kernel_launch(void* const* d_in, const int* in_sizes, int n_in,
                              void* d_out, int out_size)
{
    (void)in_sizes; (void)n_in; (void)out_size;

    const float* x     = (const float*)d_in[0];
    const float* Wq    = (const float*)d_in[1];
    const float* Wk    = (const float*)d_in[2];
    const float* Wv    = (const float*)d_in[3];
    const float* Wo    = (const float*)d_in[4];
    const float* g1    = (const float*)d_in[5];
    const float* be1   = (const float*)d_in[6];
    const float* w_in  = (const float*)d_in[7];
    const float* b_in  = (const float*)d_in[8];
    const float* w_out = (const float*)d_in[9];
    const float* b_out = (const float*)d_in[10];
    const float* g2    = (const float*)d_in[11];
    const float* be2   = (const float*)d_in[12];
    float* out = (float*)d_out;

    float *tmp, *x1;
    __half *xf, *qkvf, *af, *x1f, *h1f;
    __half *wqkvf, *wof, *winf, *woutf;
    cudaGetSymbolAddress((void**)&tmp,  g_tmp);
    cudaGetSymbolAddress((void**)&x1,   g_x1);
    cudaGetSymbolAddress((void**)&xf,   g_xf);
    cudaGetSymbolAddress((void**)&qkvf, g_qkvf);
    cudaGetSymbolAddress((void**)&af,   g_af);
    cudaGetSymbolAddress((void**)&x1f,  g_x1f);
    cudaGetSymbolAddress((void**)&h1f,  g_h1f);
    cudaGetSymbolAddress((void**)&wqkvf, g_wqkvf);
    cudaGetSymbolAddress((void**)&wof,   g_wof);
    cudaGetSymbolAddress((void**)&winf,  g_winf);
    cudaGetSymbolAddress((void**)&woutf, g_woutf);

    // one-time side stream + events (created on first, non-captured, call)
    static cudaStream_t s2 = nullptr;
    static cudaEvent_t evFork = nullptr, evJoin = nullptr;
    if (!s2) {
        cudaStreamCreateWithFlags(&s2, cudaStreamNonBlocking);
        cudaEventCreateWithFlags(&evFork, cudaEventDisableTiming);
        cudaEventCreateWithFlags(&evJoin, cudaEventDisableTiming);
    }

    cudaFuncSetAttribute(flash_tc_kernel, cudaFuncAttributeMaxDynamicSharedMemorySize, FA_SMEM);
    cudaFuncSetAttribute(gemm1_kernel<false,false,false,true>, cudaFuncAttributeMaxDynamicSharedMemorySize, G1_SMEM);
    cudaFuncSetAttribute(gemm1_kernel<false,false,true,false>, cudaFuncAttributeMaxDynamicSharedMemorySize, G1_SMEM);
    cudaFuncSetAttribute(gemm1_kernel<true,true,false,true>,   cudaFuncAttributeMaxDynamicSharedMemorySize, G1_SMEM);
    cudaFuncSetAttribute(gemm1_kernel<true,false,true,false>,  cudaFuncAttributeMaxDynamicSharedMemorySize, G1_SMEM);

    // ---- prep on main stream: convert x, QKV weights, Wo ----
    fconvert_kernel<<<MM*DD/1024, 256>>>(x, xf, MM*DD/4);
    qkvT_kernel<<<dim3(2, 32, 48), dim3(32, 8)>>>(Wq, Wk, Wv, wqkvf);
    wsplitWo_kernel<<<1024, dim3(32, 8)>>>(Wo);

    // ---- fork: FFN weight transpose overlaps QKV+attention ----
    cudaEventRecord(evFork, 0);
    cudaStreamWaitEvent(s2, evFork, 0);
    wsplit2_kernel<<<8192, dim3(32, 8), 0, s2>>>(w_in, w_out);
    cudaEventRecord(evJoin, s2);

    // ---- 1) fused QKV projection (single fp16) ----
    gemm1_kernel<false,false,false,true><<<dim3(3072/128, MM/128), 256, G1_SMEM>>>(
        xf, wqkvf, nullptr, nullptr, qkvf, MM, 3072, 1024);

    // ---- 2) causal flash attention (single fp16) ----
    flash_tc_kernel<<<dim3(SS/256, BB*HH), 256, FA_SMEM>>>();

    // ---- 3) output projection ----
    gemm1_kernel<false,false,true,false><<<dim3(1024/128, MM/128), 256, G1_SMEM>>>(
        af, wof, nullptr, tmp, nullptr, MM, 1024, 1024);

    // ---- 4) LN1 (x + attn@Wo) -> fp32 + fp16 ----
    ln_kernel<true><<<MM, 256>>>(x, tmp, g1, be1, x1, x1f);

    // join: FFN weights ready before step 5
    cudaStreamWaitEvent(0, evJoin, 0);

    // ---- 5) FFN up + bias + ReLU -> fp16 ----
    gemm1_kernel<true,true,false,true><<<dim3(4096/128, MM/128), 256, G1_SMEM>>>(
        x1f, winf, b_in, nullptr, h1f, MM, 4096, 1024);

    // ---- 6) FFN down + bias -> fp32 ----
    gemm1_kernel<true,false,true,false><<<dim3(1024/128, MM/128), 256, G1_SMEM>>>(
        h1f, woutf, b_out, tmp, nullptr, MM, 1024, 4096);

    // ---- 7) LN2 -> output ----
    ln_kernel<false><<<MM, 256>>>(x1, tmp, g2, be2, out, nullptr);
}

// round 16
// speedup vs baseline: 1.1040x; 1.1040x over previous
#include <cuda_runtime.h>
#include <cuda_bf16.h>
#include <cuda_fp16.h>
#include <math.h>

// Problem constants
#define BB   4
#define SS   2048
#define DD   1024
#define HH   16
#define HDIM 64
#define FF   4096
#define MM   (BB*SS)   // 8192 rows
#define LN_EPS 1e-5f

// ===================== low-level helpers =====================
__device__ __forceinline__ unsigned int smem_u32(const void* p) {
    unsigned int a;
    asm("{ .reg .u64 t; cvta.to.shared.u64 t, %1; cvt.u32.u64 %0, t; }" : "=r"(a) : "l"(p));
    return a;
}
__device__ __forceinline__ void cp16(unsigned int s, const void* g) {
    asm volatile("cp.async.cg.shared.global [%0], [%1], 16;" :: "r"(s), "l"(g));
}
#define CP_COMMIT() asm volatile("cp.async.commit_group;" ::: "memory")
#define CP_WAIT1()  asm volatile("cp.async.wait_group 1;" ::: "memory")
#define CP_WAIT2()  asm volatile("cp.async.wait_group 2;" ::: "memory")
#define CP_WAIT0()  asm volatile("cp.async.wait_group 0;" ::: "memory")

__device__ __forceinline__ void ldsm4(unsigned int* r, unsigned int addr) {
    asm volatile("ldmatrix.sync.aligned.m8n8.x4.shared.b16 {%0,%1,%2,%3}, [%4];"
        : "=r"(r[0]), "=r"(r[1]), "=r"(r[2]), "=r"(r[3]) : "r"(addr));
}
__device__ __forceinline__ void ldsm4t(unsigned int* r, unsigned int addr) {
    asm volatile("ldmatrix.sync.aligned.m8n8.x4.trans.shared.b16 {%0,%1,%2,%3}, [%4];"
        : "=r"(r[0]), "=r"(r[1]), "=r"(r[2]), "=r"(r[3]) : "r"(addr));
}
__device__ __forceinline__ void mma_f16(float* c, const unsigned int* a,
                                        unsigned int b0, unsigned int b1) {
    asm volatile("mma.sync.aligned.m16n8k16.row.col.f32.f16.f16.f32 "
        "{%0,%1,%2,%3}, {%4,%5,%6,%7}, {%8,%9}, {%0,%1,%2,%3};"
        : "+f"(c[0]), "+f"(c[1]), "+f"(c[2]), "+f"(c[3])
        : "r"(a[0]), "r"(a[1]), "r"(a[2]), "r"(a[3]), "r"(b0), "r"(b1));
}
__device__ __forceinline__ unsigned int pack_f16(__half a, __half b) {
    return (unsigned int)__half_as_ushort(a) | ((unsigned int)__half_as_ushort(b) << 16);
}
__device__ __forceinline__ unsigned int pack2f(float a, float b) {
    return pack_f16(__float2half(a), __float2half(b));
}

// ===================== scratch (device globals) =====================
__device__ __half g_xf[(size_t)MM*DD];
__device__ __half g_qkvf[(size_t)MM*3072];
__device__ __half g_af[(size_t)MM*DD];         // attention out single fp16
__device__ float g_tmp[(size_t)MM*DD];
__device__ float g_x1[(size_t)MM*DD];
__device__ __half g_x1f[(size_t)MM*DD];
__device__ __half g_h1f[(size_t)MM*FF];
// transposed single-fp16 weights ([N,K] row-major)
__device__ __half g_wqkvf[(size_t)3072*1024];
__device__ __half g_wof[(size_t)1024*1024];
__device__ __half g_winf[(size_t)4096*1024];
__device__ __half g_woutf[(size_t)1024*4096];

// ===================== prep kernels =====================
__global__ void fconvert_kernel(const float* __restrict__ in,
                                __half* __restrict__ o, int n4)
{
    int i = blockIdx.x * blockDim.x + threadIdx.x;
    if (i >= n4) return;
    float4 v = ((const float4*)in)[i];
    ((uint2*)o)[i] = make_uint2(pack2f(v.x, v.y), pack2f(v.z, v.w));
}

// transpose one 32x32 block of W [K,N] -> single fp16 T [N,K]
__device__ __forceinline__ void wsingle_block(const float* __restrict__ W,
                                              __half* __restrict__ T,
                                              int K, int N, int k0, int n0,
                                              float t[32][33])
{
    int tx = threadIdx.x, ty = threadIdx.y;
    #pragma unroll
    for (int i = 0; i < 32; i += 8)
        t[ty + i][tx] = W[(size_t)(k0 + ty + i) * N + n0 + tx];
    __syncthreads();
    #pragma unroll
    for (int i = 0; i < 32; i += 8) {
        float v = t[tx][ty + i];
        T[(size_t)(n0 + ty + i) * K + k0 + tx] = __float2half(v);
    }
}

// merged: Wo fp16 (1024 blocks), w_in fp16 (4096), w_out fp16 (4096)
__global__ void wsplit3_kernel(const float* __restrict__ Wo,
                               const float* __restrict__ Win,
                               const float* __restrict__ Wout)
{
    __shared__ float t[32][33];
    int idx = blockIdx.x;
    if (idx < 1024) {
        wsingle_block(Wo, g_wof, 1024, 1024,
                      (idx >> 5) * 32, (idx & 31) * 32, t);
    } else if (idx < 1024 + 4096) {
        int i2 = idx - 1024;
        wsingle_block(Win, g_winf, 1024, 4096,
                      (i2 >> 7) * 32, (i2 & 127) * 32, t);
    } else {
        int i2 = idx - 5120;
        wsingle_block(Wout, g_woutf, 4096, 1024,
                      (i2 >> 5) * 32, (i2 & 31) * 32, t);
    }
}

// Wq/Wk/Wv [H,D,HD] -> combined transposed single fp16 [3072, 1024]
__global__ void qkvT_kernel(const float* __restrict__ Wq,
                            const float* __restrict__ Wk,
                            const float* __restrict__ Wv,
                            __half* __restrict__ T)
{
    __shared__ float t[32][33];
    int z = blockIdx.z;
    int mat = z / HH, h = z - mat * HH;
    const float* W = (mat == 0 ? Wq : mat == 1 ? Wk : Wv) + (size_t)h * DD * HDIM;
    int k0 = blockIdx.y * 32, e0 = blockIdx.x * 32;
    int tx = threadIdx.x, ty = threadIdx.y;
    #pragma unroll
    for (int i = 0; i < 32; i += 8)
        t[ty + i][tx] = W[(size_t)(k0 + ty + i) * HDIM + e0 + tx];
    __syncthreads();
    int nbase = mat * 1024 + h * HDIM;
    #pragma unroll
    for (int i = 0; i < 32; i += 8) {
        float v = t[tx][ty + i];
        T[(size_t)(nbase + e0 + ty + i) * DD + k0 + tx] = __float2half(v);
    }
}

// swizzled byte offset for (row, 16B-chunk ck) within a 128B-row matrix
#define GSW(r, ck) ((unsigned int)((r) * 128 + ((((ck) ^ ((r) & 7))) << 4)))

// ===================== single-fp16 GEMM, 2 CTAs/SM ==============
// D = A*B. Block 128x128, 256 threads (8 warps, warp 64x32), K-chunk 64,
// 3-stage (32KB/stage, 96KB total) -> 2 CTAs co-resident per SM.
#define G1_A  0
#define G1_B  16384
#define G1_STG 32768
#define G1_SMEM (3*G1_STG)     // 98304

template<bool BIAS, bool RELU, bool F32OUT, bool HALFOUT>
__global__ void __launch_bounds__(256, 2) gemm1_kernel(
    const __half* __restrict__ A,
    const __half* __restrict__ BT,
    const float* __restrict__ bias,
    float* __restrict__ C,
    __half* __restrict__ Ch,
    int M, int N, int K)
{
    extern __shared__ __align__(128) char smem[];
    const unsigned int sb = smem_u32(smem);
    const int tid = threadIdx.x;
    const int row0 = blockIdx.y * 128;
    const int col0 = blockIdx.x * 128;

    const int wid = tid >> 5, lane = tid & 31;
    const int wm0 = (wid & 1) * 64, wn0 = (wid >> 1) * 32;
    const int lr = lane & 15, lh = lane >> 4;

    auto load_stage = [&](int c, int s) {
        unsigned int base = sb + s * G1_STG;
        int k0 = c * 64;
        #pragma unroll
        for (int i = 0; i < 4; i++) {
            int lin = tid + (i << 8);            // 0..1023 : A rows 0..127
            int r = lin >> 3, ck = lin & 7;
            unsigned int so = GSW(r, ck);
            cp16(base + G1_A + so, A + (size_t)(row0 + r) * K + k0 + ck * 8);
        }
        #pragma unroll
        for (int i = 0; i < 4; i++) {
            int lin = tid + (i << 8);            // 0..1023 : B rows 0..127
            int r = lin >> 3, ck = lin & 7;
            unsigned int so = GSW(r, ck);
            cp16(base + G1_B + so, BT + (size_t)(col0 + r) * K + k0 + ck * 8);
        }
        CP_COMMIT();
    };

    float acc[4][4][4] = {};

    load_stage(0, 0);
    load_stage(1, 1);
    load_stage(2, 2);

    const int NC = K >> 6;
    for (int c = 0; c < NC; c++) {
        CP_WAIT2();
        __syncthreads();

        unsigned int base = sb + (c % 3) * G1_STG;
        #pragma unroll
        for (int ks = 0; ks < 4; ks++) {
            unsigned int a_r[4][4], b_r[2][4];
            #pragma unroll
            for (int mt = 0; mt < 4; mt++) {
                int r = wm0 + mt*16 + lr;
                unsigned int ro = GSW(r, ks*2 + lh);
                ldsm4(a_r[mt], base + G1_A + ro);
            }
            #pragma unroll
            for (int bt = 0; bt < 2; bt++) {
                int r = wn0 + bt*16 + lr;
                unsigned int ro = GSW(r, ks*2 + lh);
                ldsm4(b_r[bt], base + G1_B + ro);
            }
            #pragma unroll
            for (int mt = 0; mt < 4; mt++)
                #pragma unroll
                for (int nt = 0; nt < 4; nt++)
                    mma_f16(acc[mt][nt], a_r[mt], b_r[nt>>1][nt&1], b_r[nt>>1][(nt&1)+2]);
        }

        __syncthreads();
        if (c + 3 < NC) load_stage(c + 3, (c + 3) % 3);
    }

    // ---- epilogue ----
    const int gq = lane >> 2, pq = lane & 3;
    #pragma unroll
    for (int mt = 0; mt < 4; mt++) {
        #pragma unroll
        for (int nt = 0; nt < 4; nt++) {
            int col = col0 + wn0 + nt*8 + pq*2;
            float b0 = 0.f, b1 = 0.f;
            if (BIAS) { b0 = bias[col]; b1 = bias[col+1]; }
            #pragma unroll
            for (int h2 = 0; h2 < 2; h2++) {
                int row = row0 + wm0 + mt*16 + gq + h2*8;
                float v0 = acc[mt][nt][h2*2+0] + b0;
                float v1 = acc[mt][nt][h2*2+1] + b1;
                if (RELU) { v0 = fmaxf(v0, 0.f); v1 = fmaxf(v1, 0.f); }
                if (F32OUT)
                    *(float2*)(C + (size_t)row * N + col) = make_float2(v0, v1);
                if (HALFOUT)
                    *(unsigned int*)(Ch + (size_t)row * N + col) = pack2f(v0, v1);
            }
        }
    }
}

// ===================== tensor-core causal flash attention (single fp16) =======
// QK: 1-term; PV: 1-term. 2 CTAs/SM (55KB smem each).
#define AP 144
#define KMAT 9216              // 64*AP
#define QMAT 18432             // 128*AP
#define FA_STG (2*KMAT)        // 18432
#define FA_SMEM (QMAT + 2*FA_STG)   // 55296

__global__ void __launch_bounds__(256, 2) flash_tc_kernel()
{
    const int pid = blockIdx.x, bh = blockIdx.y;
    const int b = bh >> 4, h = bh & 15;
    const int tid = threadIdx.x, wid = tid >> 5, lane = tid & 31;
    const int wm = wid * 16;
    const int lr = lane & 15, lh = lane >> 4;

    extern __shared__ __align__(16) char smem[];
    const unsigned int sb = smem_u32(smem);
    const unsigned int sQ = sb;

    for (int run = 0; run < 2; run++) {
        const int qt0 = run ? (15 - pid) : pid;
        const int NKT = 2 * qt0 + 2;

        __syncthreads();

        {
            const __half* q = g_qkvf + (size_t)(b*SS + qt0*128)*3072 + h*HDIM;
            #pragma unroll
            for (int i = 0; i < 4; i++) {
                int lin = tid + (i << 8);
                int r = lin >> 3, ck = lin & 7;
                cp16(sQ + r*AP + ck*16, q + (size_t)r*3072 + ck*8);
            }
            CP_COMMIT();
        }

        auto load_kv = [&](int kt, int s) {
            unsigned int base = sb + QMAT + s * FA_STG;
            size_t rowb = (size_t)(b*SS + kt*64)*3072;
            const __half* k = g_qkvf + rowb + 1024 + h*HDIM;
            const __half* v = g_qkvf + rowb + 2048 + h*HDIM;
            #pragma unroll
            for (int i = 0; i < 2; i++) {
                int lin = tid + (i << 8);
                int r = lin >> 3, ck = lin & 7;
                unsigned int so = r*AP + ck*16;
                size_t g = (size_t)r*3072 + ck*8;
                cp16(base + so,        k + g);
                cp16(base + KMAT + so, v + g);
            }
            CP_COMMIT();
        };

        load_kv(0, 0);
        load_kv(1, 1);

        float o[8][4] = {};
        float m0 = -1e30f, m1 = -1e30f, l0 = 0.f, l1 = 0.f;

        for (int kt = 0; kt < NKT; kt++) {
            if (kt < NKT - 1) CP_WAIT1(); else CP_WAIT0();
            __syncthreads();

            const unsigned int kb = sb + QMAT + (kt & 1) * FA_STG;

            float sc[8][4] = {};
            #pragma unroll
            for (int kd = 0; kd < 4; kd++) {
                unsigned int aq[4];
                unsigned int qro = (unsigned int)(wm + lr)*AP + (kd*2 + lh)*16;
                ldsm4(aq, sQ + qro);
                #pragma unroll
                for (int g = 0; g < 4; g++) {
                    unsigned int rk[4];
                    unsigned int kro = (unsigned int)(g*16 + lr)*AP + (kd*2 + lh)*16;
                    ldsm4(rk, kb + kro);
                    mma_f16(sc[2*g],   aq, rk[0], rk[2]);
                    mma_f16(sc[2*g+1], aq, rk[1], rk[3]);
                }
            }

            if (kt >= 2*qt0) {
                const int grow0 = qt0*128 + wm + (lane >> 2);
                const int gc0 = kt*64 + (lane & 3)*2;
                #pragma unroll
                for (int nt = 0; nt < 8; nt++) {
                    int c0l = gc0 + nt*8;
                    sc[nt][0] = (c0l     > grow0)   ? -1e30f : sc[nt][0]*0.125f;
                    sc[nt][1] = (c0l + 1 > grow0)   ? -1e30f : sc[nt][1]*0.125f;
                    sc[nt][2] = (c0l     > grow0+8) ? -1e30f : sc[nt][2]*0.125f;
                    sc[nt][3] = (c0l + 1 > grow0+8) ? -1e30f : sc[nt][3]*0.125f;
                }
            } else {
                #pragma unroll
                for (int nt = 0; nt < 8; nt++) {
                    sc[nt][0] *= 0.125f; sc[nt][1] *= 0.125f;
                    sc[nt][2] *= 0.125f; sc[nt][3] *= 0.125f;
                }
            }

            float mx0 = -1e30f, mx1 = -1e30f;
            #pragma unroll
            for (int nt = 0; nt < 8; nt++) {
                mx0 = fmaxf(mx0, fmaxf(sc[nt][0], sc[nt][1]));
                mx1 = fmaxf(mx1, fmaxf(sc[nt][2], sc[nt][3]));
            }
            mx0 = fmaxf(mx0, __shfl_xor_sync(0xffffffffu, mx0, 1));
            mx0 = fmaxf(mx0, __shfl_xor_sync(0xffffffffu, mx0, 2));
            mx1 = fmaxf(mx1, __shfl_xor_sync(0xffffffffu, mx1, 1));
            mx1 = fmaxf(mx1, __shfl_xor_sync(0xffffffffu, mx1, 2));
            float mn0 = fmaxf(m0, mx0), mn1 = fmaxf(m1, mx1);
            float cf0 = __expf(m0 - mn0), cf1 = __expf(m1 - mn1);
            m0 = mn0; m1 = mn1;
            float s0 = 0.f, s1 = 0.f;
            #pragma unroll
            for (int nt = 0; nt < 8; nt++) {
                sc[nt][0] = __expf(sc[nt][0] - mn0);
                sc[nt][1] = __expf(sc[nt][1] - mn0);
                sc[nt][2] = __expf(sc[nt][2] - mn1);
                sc[nt][3] = __expf(sc[nt][3] - mn1);
                s0 += sc[nt][0] + sc[nt][1];
                s1 += sc[nt][2] + sc[nt][3];
            }
            s0 += __shfl_xor_sync(0xffffffffu, s0, 1);
            s0 += __shfl_xor_sync(0xffffffffu, s0, 2);
            s1 += __shfl_xor_sync(0xffffffffu, s1, 1);
            s1 += __shfl_xor_sync(0xffffffffu, s1, 2);
            l0 = l0 * cf0 + s0;
            l1 = l1 * cf1 + s1;
            #pragma unroll
            for (int dt = 0; dt < 8; dt++) {
                o[dt][0] *= cf0; o[dt][1] *= cf0;
                o[dt][2] *= cf1; o[dt][3] *= cf1;
            }

            #pragma unroll
            for (int j = 0; j < 4; j++) {
                unsigned int ph[4];
                ph[0] = pack2f(sc[2*j][0],   sc[2*j][1]);
                ph[1] = pack2f(sc[2*j][2],   sc[2*j][3]);
                ph[2] = pack2f(sc[2*j+1][0], sc[2*j+1][1]);
                ph[3] = pack2f(sc[2*j+1][2], sc[2*j+1][3]);
                #pragma unroll
                for (int g = 0; g < 4; g++) {
                    unsigned int rv[4];
                    unsigned int vro = (unsigned int)(j*16 + lr)*AP + (g*2 + lh)*16;
                    ldsm4t(rv, kb + KMAT + vro);
                    mma_f16(o[2*g],   ph, rv[0], rv[1]);
                    mma_f16(o[2*g+1], ph, rv[2], rv[3]);
                }
            }

            __syncthreads();
            if (kt + 2 < NKT) load_kv(kt + 2, kt & 1);
        }

        const float inv0 = 1.f / l0, inv1 = 1.f / l1;
        const int row0g = qt0*128 + wm + (lane >> 2);
        __half* op = g_af + ((size_t)bh*SS)*HDIM;
        #pragma unroll
        for (int dt = 0; dt < 8; dt++) {
            int d = dt*8 + (lane & 3)*2;
            *(unsigned int*)(op + (size_t)row0g*HDIM + d) =
                pack2f(o[dt][0]*inv0, o[dt][1]*inv0);
            *(unsigned int*)(op + (size_t)(row0g+8)*HDIM + d) =
                pack2f(o[dt][2]*inv1, o[dt][3]*inv1);
        }
    }
}

// ===================== LayerNorm =====================
__device__ __forceinline__ float blk_sum(float v, float* sred)
{
    #pragma unroll
    for (int o = 16; o; o >>= 1) v += __shfl_xor_sync(0xffffffffu, v, o);
    int w = threadIdx.x >> 5;
    if ((threadIdx.x & 31) == 0) sred[w] = v;
    __syncthreads();
    float t = (threadIdx.x < 8) ? sred[threadIdx.x] : 0.f;
    if (threadIdx.x < 32) {
        #pragma unroll
        for (int o = 4; o; o >>= 1) t += __shfl_xor_sync(0xffffffffu, t, o);
        if (threadIdx.x == 0) sred[0] = t;
    }
    __syncthreads();
    float r = sred[0];
    __syncthreads();
    return r;
}

template<bool OUTH>
__global__ void ln_kernel(const float* __restrict__ resid,
                          const float* __restrict__ y,
                          const float* __restrict__ gamma,
                          const float* __restrict__ beta,
                          float* __restrict__ outf,
                          __half* __restrict__ oh)
{
    __shared__ float sred[32];
    const int row = blockIdx.x;
    const int tid = threadIdx.x;

    float4 a = ((const float4*)(resid + (size_t)row * DD))[tid];
    float4 b = ((const float4*)(y     + (size_t)row * DD))[tid];
    float4 v = make_float4(a.x + b.x, a.y + b.y, a.z + b.z, a.w + b.w);

    float total = blk_sum(v.x + v.y + v.z + v.w, sred);
    float mu = total * (1.f / DD);

    float dx = v.x - mu, dy = v.y - mu, dz = v.z - mu, dw = v.w - mu;
    float tot2 = blk_sum(dx*dx + dy*dy + dz*dz + dw*dw, sred);
    float inv = rsqrtf(tot2 * (1.f / DD) + LN_EPS);

    float4 g = ((const float4*)gamma)[tid];
    float4 be = ((const float4*)beta)[tid];
    float ov[4];
    ov[0] = dx * inv * g.x + be.x;
    ov[1] = dy * inv * g.y + be.y;
    ov[2] = dz * inv * g.z + be.z;
    ov[3] = dw * inv * g.w + be.w;
    ((float4*)(outf + (size_t)row * DD))[tid] = make_float4(ov[0], ov[1], ov[2], ov[3]);

    if (OUTH) {
        *(uint2*)(oh + (size_t)row * DD + tid * 4) =
            make_uint2(pack2f(ov[0], ov[1]), pack2f(ov[2], ov[3]));
    }
}

// ===================== launch =====================
extern "C" void kernel_launch(void* const* d_in, const int* in_sizes, int n_in,
                              void* d_out, int out_size)
{
    (void)in_sizes; (void)n_in; (void)out_size;

    const float* x     = (const float*)d_in[0];
    const float* Wq    = (const float*)d_in[1];
    const float* Wk    = (const float*)d_in[2];
    const float* Wv    = (const float*)d_in[3];
    const float* Wo    = (const float*)d_in[4];
    const float* g1    = (const float*)d_in[5];
    const float* be1   = (const float*)d_in[6];
    const float* w_in  = (const float*)d_in[7];
    const float* b_in  = (const float*)d_in[8];
    const float* w_out = (const float*)d_in[9];
    const float* b_out = (const float*)d_in[10];
    const float* g2    = (const float*)d_in[11];
    const float* be2   = (const float*)d_in[12];
    float* out = (float*)d_out;

    float *tmp, *x1;
    __half *xf, *qkvf, *af, *x1f, *h1f;
    __half *wqkvf, *wof, *winf, *woutf;
    cudaGetSymbolAddress((void**)&tmp,  g_tmp);
    cudaGetSymbolAddress((void**)&x1,   g_x1);
    cudaGetSymbolAddress((void**)&xf,   g_xf);
    cudaGetSymbolAddress((void**)&qkvf, g_qkvf);
    cudaGetSymbolAddress((void**)&af,   g_af);
    cudaGetSymbolAddress((void**)&x1f,  g_x1f);
    cudaGetSymbolAddress((void**)&h1f,  g_h1f);
    cudaGetSymbolAddress((void**)&wqkvf, g_wqkvf);
    cudaGetSymbolAddress((void**)&wof,   g_wof);
    cudaGetSymbolAddress((void**)&winf,  g_winf);
    cudaGetSymbolAddress((void**)&woutf, g_woutf);

    cudaFuncSetAttribute(flash_tc_kernel, cudaFuncAttributeMaxDynamicSharedMemorySize, FA_SMEM);
    cudaFuncSetAttribute(gemm1_kernel<false,false,false,true>, cudaFuncAttributeMaxDynamicSharedMemorySize, G1_SMEM);
    cudaFuncSetAttribute(gemm1_kernel<false,false,true,false>, cudaFuncAttributeMaxDynamicSharedMemorySize, G1_SMEM);
    cudaFuncSetAttribute(gemm1_kernel<true,true,false,true>,   cudaFuncAttributeMaxDynamicSharedMemorySize, G1_SMEM);
    cudaFuncSetAttribute(gemm1_kernel<true,false,true,false>,  cudaFuncAttributeMaxDynamicSharedMemorySize, G1_SMEM);

    // ---- prep: convert x; transpose weights to single fp16 ----
    fconvert_kernel<<<MM*DD/1024, 256>>>(x, xf, MM*DD/4);
    qkvT_kernel<<<dim3(2, 32, 48), dim3(32, 8)>>>(Wq, Wk, Wv, wqkvf);
    wsplit3_kernel<<<9216, dim3(32, 8)>>>(Wo, w_in, w_out);

    // ---- 1) fused QKV projection (single fp16) ----
    gemm1_kernel<false,false,false,true><<<dim3(3072/128, MM/128), 256, G1_SMEM>>>(
        xf, wqkvf, nullptr, nullptr, qkvf, MM, 3072, 1024);

    // ---- 2) causal flash attention (single fp16, 2 CTAs/SM) ----
    flash_tc_kernel<<<dim3(SS/256, BB*HH), 256, FA_SMEM>>>();

    // ---- 3) output projection ----
    gemm1_kernel<false,false,true,false><<<dim3(1024/128, MM/128), 256, G1_SMEM>>>(
        af, wof, nullptr, tmp, nullptr, MM, 1024, 1024);

    // ---- 4) LN1 (x + attn@Wo) -> fp32 + fp16 ----
    ln_kernel<true><<<MM, 256>>>(x, tmp, g1, be1, x1, x1f);

    // ---- 5) FFN up + bias + ReLU -> fp16 ----
    gemm1_kernel<true,true,false,true><<<dim3(4096/128, MM/128), 256, G1_SMEM>>>(
        x1f, winf, b_in, nullptr, h1f, MM, 4096, 1024);

    // ---- 6) FFN down + bias -> fp32 ----
    gemm1_kernel<true,false,true,false><<<dim3(1024/128, MM/128), 256, G1_SMEM>>>(
        h1f, woutf, b_out, tmp, nullptr, MM, 1024, 4096);

    // ---- 7) LN2 -> output ----
    ln_kernel<false><<<MM, 256>>>(x1, tmp, g2, be2, out, nullptr);
}